// round 3
// baseline (speedup 1.0000x reference)
#include <cuda_runtime.h>

// out[row, e] = cos(x[row, 1]) * W_dec[e] + b_dec[e]
// x: (n_rows, 1024) fp32 ; W_dec: (1024,) ; b_dec: (1024,) ; out: (n_rows, 1024)
// Store-bound. R2: 256-bit stores (STG.E.256, sm_100+), 16 rows/block, 128 thr.

#define EMBED 1024
#define VEC 8                      // float v8 = 256-bit store
#define THREADS (EMBED / VEC)      // 128 threads cover one row per store round
#define ROWS_PER_BLOCK 16

__device__ __forceinline__ void st_v8_cs(float* p,
                                         float a, float b, float c, float d,
                                         float e, float f, float g, float h)
{
    asm volatile("st.global.cs.v8.f32 [%0], {%1,%2,%3,%4,%5,%6,%7,%8};"
                 :: "l"(p), "f"(a), "f"(b), "f"(c), "f"(d),
                    "f"(e), "f"(f), "f"(g), "f"(h)
                 : "memory");
}

__global__ __launch_bounds__(THREADS)
void vql_kernel(const float* __restrict__ x,
                const float* __restrict__ W,
                const float* __restrict__ b,
                float* __restrict__ out,
                int n_rows)
{
    __shared__ float s_cos[ROWS_PER_BLOCK];

    const int tid  = threadIdx.x;
    const int row0 = blockIdx.x * ROWS_PER_BLOCK;

    // Threads 0..15 compute cos(x[row,1]) for this block's rows.
    if (tid < ROWS_PER_BLOCK) {
        int r = row0 + tid;
        float v = 0.0f;
        if (r < n_rows)
            v = __ldg(&x[(size_t)r * EMBED + 1]);
        s_cos[tid] = cosf(v);
    }

    // W/b chunk for this thread (8 floats each), held in registers.
    const float4 w0 = __ldg(reinterpret_cast<const float4*>(W) + 2 * tid);
    const float4 w1 = __ldg(reinterpret_cast<const float4*>(W) + 2 * tid + 1);
    const float4 b0 = __ldg(reinterpret_cast<const float4*>(b) + 2 * tid);
    const float4 b1 = __ldg(reinterpret_cast<const float4*>(b) + 2 * tid + 1);

    __syncthreads();

    float* o = out + (size_t)row0 * EMBED + tid * VEC;

    if (row0 + ROWS_PER_BLOCK <= n_rows) {
        #pragma unroll
        for (int i = 0; i < ROWS_PER_BLOCK; ++i) {
            const float c = s_cos[i];
            st_v8_cs(o + (size_t)i * EMBED,
                     fmaf(c, w0.x, b0.x), fmaf(c, w0.y, b0.y),
                     fmaf(c, w0.z, b0.z), fmaf(c, w0.w, b0.w),
                     fmaf(c, w1.x, b1.x), fmaf(c, w1.y, b1.y),
                     fmaf(c, w1.z, b1.z), fmaf(c, w1.w, b1.w));
        }
    } else {
        for (int i = 0; i < ROWS_PER_BLOCK; ++i) {
            if (row0 + i >= n_rows) break;
            const float c = s_cos[i];
            st_v8_cs(o + (size_t)i * EMBED,
                     fmaf(c, w0.x, b0.x), fmaf(c, w0.y, b0.y),
                     fmaf(c, w0.z, b0.z), fmaf(c, w0.w, b0.w),
                     fmaf(c, w1.x, b1.x), fmaf(c, w1.y, b1.y),
                     fmaf(c, w1.z, b1.z), fmaf(c, w1.w, b1.w));
        }
    }
}

extern "C" void kernel_launch(void* const* d_in, const int* in_sizes, int n_in,
                              void* d_out, int out_size)
{
    const float* x = (const float*)d_in[0];   // (32768, 1024)
    const float* W = (const float*)d_in[1];   // 1024 floats
    const float* b = (const float*)d_in[2];   // 1024 floats
    float* out = (float*)d_out;

    const int n_rows = in_sizes[0] / EMBED;                            // 32768
    const int grid = (n_rows + ROWS_PER_BLOCK - 1) / ROWS_PER_BLOCK;   // 2048

    vql_kernel<<<grid, THREADS>>>(x, W, b, out, n_rows);
}

// round 4
// speedup vs baseline: 1.0218x; 1.0218x over previous
#include <cuda_runtime.h>

// out[row, e] = cos(x[row, 1]) * W_dec[e] + b_dec[e]
// x: (32768, 1024) fp32 ; W_dec,b_dec: (1024,) ; out: (32768, 1024)
// Store-bound, L2-absorbed writes; steady-state floor = DRAM write BW.
// R3: single balanced wave (148*8 blocks), grid-stride over 4-row groups,
//     float4 stcs stores, no smem/syncthreads.

#define EMBED        1024
#define VEC          4
#define THREADS      (EMBED / VEC)   // 256: one row per store round
#define ROWS_PER_IT  4
#define SM_COUNT     148
#define BLOCKS_PER_SM 8
#define GRID         (SM_COUNT * BLOCKS_PER_SM)  // 1184 = one full wave

__global__ __launch_bounds__(THREADS, BLOCKS_PER_SM)
void vql_kernel(const float* __restrict__ x,
                const float* __restrict__ W,
                const float* __restrict__ b,
                float* __restrict__ out,
                int n_rows)
{
    const int tid = threadIdx.x;

    // This thread's 4 output columns, register-resident for the whole kernel.
    const float4 w4 = __ldg(reinterpret_cast<const float4*>(W) + tid);
    const float4 b4 = __ldg(reinterpret_cast<const float4*>(b) + tid);

    const int n_groups = n_rows / ROWS_PER_IT;   // 8192 (n_rows % 4 == 0)

    for (int g = blockIdx.x; g < n_groups; g += gridDim.x) {
        const int row0 = g * ROWS_PER_IT;

        // Warp-uniform loads (1 sector/warp, L2-hot across graph replays).
        const float x0 = __ldg(&x[(size_t)(row0 + 0) * EMBED + 1]);
        const float x1 = __ldg(&x[(size_t)(row0 + 1) * EMBED + 1]);
        const float x2 = __ldg(&x[(size_t)(row0 + 2) * EMBED + 1]);
        const float x3 = __ldg(&x[(size_t)(row0 + 3) * EMBED + 1]);

        const float c0 = cosf(x0);
        const float c1 = cosf(x1);
        const float c2 = cosf(x2);
        const float c3 = cosf(x3);

        float4* o = reinterpret_cast<float4*>(out)
                  + (size_t)row0 * (EMBED / VEC) + tid;

        float4 v0, v1, v2, v3;
        v0.x = fmaf(c0, w4.x, b4.x); v0.y = fmaf(c0, w4.y, b4.y);
        v0.z = fmaf(c0, w4.z, b4.z); v0.w = fmaf(c0, w4.w, b4.w);
        v1.x = fmaf(c1, w4.x, b4.x); v1.y = fmaf(c1, w4.y, b4.y);
        v1.z = fmaf(c1, w4.z, b4.z); v1.w = fmaf(c1, w4.w, b4.w);
        v2.x = fmaf(c2, w4.x, b4.x); v2.y = fmaf(c2, w4.y, b4.y);
        v2.z = fmaf(c2, w4.z, b4.z); v2.w = fmaf(c2, w4.w, b4.w);
        v3.x = fmaf(c3, w4.x, b4.x); v3.y = fmaf(c3, w4.y, b4.y);
        v3.z = fmaf(c3, w4.z, b4.z); v3.w = fmaf(c3, w4.w, b4.w);

        // Streaming stores: write-once output, evict-first in L2.
        __stcs(o + 0 * (EMBED / VEC), v0);
        __stcs(o + 1 * (EMBED / VEC), v1);
        __stcs(o + 2 * (EMBED / VEC), v2);
        __stcs(o + 3 * (EMBED / VEC), v3);
    }
}

extern "C" void kernel_launch(void* const* d_in, const int* in_sizes, int n_in,
                              void* d_out, int out_size)
{
    const float* x = (const float*)d_in[0];
    const float* W = (const float*)d_in[1];
    const float* b = (const float*)d_in[2];
    float* out = (float*)d_out;

    const int n_rows = in_sizes[0] / EMBED;   // 32768

    vql_kernel<<<GRID, THREADS>>>(x, W, b, out, n_rows);
}

// round 5
// speedup vs baseline: 1.1544x; 1.1298x over previous
#include <cuda_runtime.h>

// out[row, e] = cos(x[row, 1]) * W_dec[e] + b_dec[e]
// x: (32768, 1024) fp32 ; W_dec,b_dec: (1024,) ; out: (32768, 1024)
// Store-bound. R4: R1 structure exactly, but ROWS_PER_BLOCK 8 -> 4
// (8192 blocks, 7 waves, ~1% tail waste vs R1's 15%).

#define EMBED 1024
#define VEC 4                    // float4
#define THREADS (EMBED / VEC)    // 256 threads cover one row per store round
#define ROWS_PER_BLOCK 4

__global__ __launch_bounds__(THREADS)
void vql_kernel(const float* __restrict__ x,
                const float* __restrict__ W,
                const float* __restrict__ b,
                float* __restrict__ out,
                int n_rows)
{
    __shared__ float s_cos[ROWS_PER_BLOCK];

    const int tid  = threadIdx.x;
    const int row0 = blockIdx.x * ROWS_PER_BLOCK;

    // Threads 0..3 compute cos(x[row,1]) for this block's rows.
    if (tid < ROWS_PER_BLOCK) {
        int r = row0 + tid;
        float v = 0.0f;
        if (r < n_rows)
            v = __ldg(&x[(size_t)r * EMBED + 1]);
        s_cos[tid] = cosf(v);
    }
    __syncthreads();

    // W/b chunk for this thread, register-resident across all 4 rows.
    const float4 w4 = __ldg(reinterpret_cast<const float4*>(W) + tid);
    const float4 b4 = __ldg(reinterpret_cast<const float4*>(b) + tid);

    float4* o = reinterpret_cast<float4*>(out) + (size_t)row0 * (EMBED / VEC) + tid;

    #pragma unroll
    for (int i = 0; i < ROWS_PER_BLOCK; ++i) {
        if (row0 + i >= n_rows) break;
        const float c = s_cos[i];
        float4 v;
        v.x = fmaf(c, w4.x, b4.x);
        v.y = fmaf(c, w4.y, b4.y);
        v.z = fmaf(c, w4.z, b4.z);
        v.w = fmaf(c, w4.w, b4.w);
        // Streaming store: output is write-once, evict-first in L2.
        __stcs(o + (size_t)i * (EMBED / VEC), v);
    }
}

extern "C" void kernel_launch(void* const* d_in, const int* in_sizes, int n_in,
                              void* d_out, int out_size)
{
    const float* x = (const float*)d_in[0];   // (32768, 1024)
    const float* W = (const float*)d_in[1];   // 1024 floats
    const float* b = (const float*)d_in[2];   // 1024 floats
    float* out = (float*)d_out;

    const int n_rows = in_sizes[0] / EMBED;                            // 32768
    const int grid = (n_rows + ROWS_PER_BLOCK - 1) / ROWS_PER_BLOCK;   // 8192

    vql_kernel<<<grid, THREADS>>>(x, W, b, out, n_rows);
}